// round 1
// baseline (speedup 1.0000x reference)
#include <cuda_runtime.h>
#include <cuda_bf16.h>

#define BN   32
#define HH   1024
#define WW   1024
#define NPIX (HH * WW)          // 1048576 pixels per batch
#define TOTAL ((size_t)BN * NPIX)

// ---- static scratch (no allocation allowed) ----
__device__ float g_bufA[TOTAL];          // 128 MB
__device__ float g_bufB[TOTAL];          // 128 MB
__device__ unsigned int g_maxbits[BN];
__device__ unsigned int g_minbits[BN];
__device__ double g_sum[BN];
__device__ float  g_scale[BN];
__device__ float  g_offset[BN];
__device__ double g_loss;

// ---------------------------------------------------------------------------
// Reset per-launch state (deterministic: runs every call)
// ---------------------------------------------------------------------------
__global__ void reset_kernel() {
    int b = threadIdx.x;
    if (b < BN) {
        g_maxbits[b] = 0u;                  // erosion >= 0
        g_minbits[b] = 0x7f800000u;         // +inf
        g_sum[b]     = 0.0;
        g_scale[b]   = 1.0f;                // iteration 0 reads bound raw
        g_offset[b]  = 0.0f;
    }
    if (b == 0) g_loss = 0.0;
}

// ---------------------------------------------------------------------------
// bound = (pred - (target==0 ? 1 : 0))^2  -> g_bufA
// ---------------------------------------------------------------------------
__global__ void __launch_bounds__(256) bound_kernel(
    const float4* __restrict__ pred, const int4* __restrict__ tgt)
{
    size_t i = (size_t)blockIdx.x * blockDim.x + threadIdx.x;   // over TOTAL/4
    float4 p = pred[i];
    int4   t = tgt[i];
    float4 o;
    o.x = p.x - (t.x == 0 ? 1.0f : 0.0f);  o.x *= o.x;
    o.y = p.y - (t.y == 0 ? 1.0f : 0.0f);  o.y *= o.y;
    o.z = p.z - (t.z == 0 ? 1.0f : 0.0f);  o.z *= o.z;
    o.w = p.w - (t.w == 0 ? 1.0f : 0.0f);  o.w *= o.w;
    reinterpret_cast<float4*>(g_bufA)[i] = o;
}

// ---------------------------------------------------------------------------
// One erosion iteration: 5-point stencil on affine-normalized input,
// erosion = max(0.2*sum - 0.5, 0), write raw erosion, reduce max/min/sum.
// DIR==0: read g_bufA write g_bufB; DIR==1: reverse.
// grid = (HH, BN), block = 256 threads, 4 px/thread (one row per block).
// ---------------------------------------------------------------------------
template <int DIR>
__global__ void __launch_bounds__(256) stencil_kernel()
{
    const float* __restrict__ in  = DIR ? g_bufB : g_bufA;
    float*       __restrict__ out = DIR ? g_bufA : g_bufB;

    const int y    = blockIdx.x;
    const int b    = blockIdx.y;
    const int t    = threadIdx.x;
    const int lane = t & 31;
    const int warp = t >> 5;
    const int x0   = t << 2;

    const size_t base = ((size_t)b * HH + y) * WW;
    const float s = g_scale[b];
    const float o = g_offset[b];

    const float* rowc = in + base;

    float4 c4 = *reinterpret_cast<const float4*>(rowc + x0);
    c4.x = fmaf(c4.x, s, o); c4.y = fmaf(c4.y, s, o);
    c4.z = fmaf(c4.z, s, o); c4.w = fmaf(c4.w, s, o);

    float4 u4 = make_float4(0.f, 0.f, 0.f, 0.f);
    if (y > 0) {
        u4 = *reinterpret_cast<const float4*>(rowc - WW + x0);
        u4.x = fmaf(u4.x, s, o); u4.y = fmaf(u4.y, s, o);
        u4.z = fmaf(u4.z, s, o); u4.w = fmaf(u4.w, s, o);
    }
    float4 d4 = make_float4(0.f, 0.f, 0.f, 0.f);
    if (y < HH - 1) {
        d4 = *reinterpret_cast<const float4*>(rowc + WW + x0);
        d4.x = fmaf(d4.x, s, o); d4.y = fmaf(d4.y, s, o);
        d4.z = fmaf(d4.z, s, o); d4.w = fmaf(d4.w, s, o);
    }

    // horizontal halo via shuffles; warp/row edges fall back to scalar loads
    float l = __shfl_up_sync(0xffffffffu, c4.w, 1);
    if (lane == 0) l = (x0 > 0) ? fmaf(rowc[x0 - 1], s, o) : 0.0f;
    float r = __shfl_down_sync(0xffffffffu, c4.x, 1);
    if (lane == 31) r = (x0 + 4 < WW) ? fmaf(rowc[x0 + 4], s, o) : 0.0f;

    float e0 = fmaxf(fmaf(0.2f, (c4.x + u4.x) + (d4.x + l)    + c4.y, -0.5f), 0.0f);
    float e1 = fmaxf(fmaf(0.2f, (c4.y + u4.y) + (d4.y + c4.x) + c4.z, -0.5f), 0.0f);
    float e2 = fmaxf(fmaf(0.2f, (c4.z + u4.z) + (d4.z + c4.y) + c4.w, -0.5f), 0.0f);
    float e3 = fmaxf(fmaf(0.2f, (c4.w + u4.w) + (d4.w + c4.z) + r,    -0.5f), 0.0f);

    *reinterpret_cast<float4*>(out + base + x0) = make_float4(e0, e1, e2, e3);

    // ---- block reduction: max / min / sum ----
    float vmax = fmaxf(fmaxf(e0, e1), fmaxf(e2, e3));
    float vmin = fminf(fminf(e0, e1), fminf(e2, e3));
    float vsum = (e0 + e1) + (e2 + e3);
    #pragma unroll
    for (int d = 16; d > 0; d >>= 1) {
        vmax  = fmaxf(vmax, __shfl_xor_sync(0xffffffffu, vmax, d));
        vmin  = fminf(vmin, __shfl_xor_sync(0xffffffffu, vmin, d));
        vsum +=             __shfl_xor_sync(0xffffffffu, vsum, d);
    }
    __shared__ float smax[8], smin[8], ssum[8];
    if (lane == 0) { smax[warp] = vmax; smin[warp] = vmin; ssum[warp] = vsum; }
    __syncthreads();
    if (warp == 0) {
        vmax = (lane < 8) ? smax[lane] : 0.0f;
        vmin = (lane < 8) ? smin[lane] : __int_as_float(0x7f800000);
        vsum = (lane < 8) ? ssum[lane] : 0.0f;
        #pragma unroll
        for (int d = 4; d > 0; d >>= 1) {
            vmax  = fmaxf(vmax, __shfl_xor_sync(0xffffffffu, vmax, d));
            vmin  = fminf(vmin, __shfl_xor_sync(0xffffffffu, vmin, d));
            vsum +=             __shfl_xor_sync(0xffffffffu, vsum, d);
        }
        if (lane == 0) {
            // values are >= 0 so float ordering == uint ordering
            atomicMax(&g_maxbits[b], __float_as_uint(vmax));
            atomicMin(&g_minbits[b], __float_as_uint(vmin));
            atomicAdd(&g_sum[b], (double)vsum);
        }
    }
}

// ---------------------------------------------------------------------------
// Per-iteration epilogue: compute normalization affine for next iteration and
// the analytic contribution of the normalized erosion to the loss sum.
// One block of 32 threads (one per batch).
// ---------------------------------------------------------------------------
__global__ void epilogue_kernel(double wgt)
{
    int b = threadIdx.x;   // 0..31
    float emax = __uint_as_float(g_maxbits[b]);
    float emin = __uint_as_float(g_minbits[b]);
    double s   = g_sum[b];
    float denom = emax - emin;

    double contrib;
    if (denom != 0.0f) {
        g_scale[b]  = 1.0f / denom;
        g_offset[b] = -emin / denom;
        contrib = (s - (double)NPIX * (double)emin) / (double)denom;
    } else {
        g_scale[b]  = 1.0f;
        g_offset[b] = 0.0f;
        contrib = s;
    }

    // reset accumulators for next iteration
    g_maxbits[b] = 0u;
    g_minbits[b] = 0x7f800000u;
    g_sum[b]     = 0.0;

    double v = contrib * wgt;
    #pragma unroll
    for (int d = 16; d > 0; d >>= 1)
        v += __shfl_xor_sync(0xffffffffu, v, d);
    if (b == 0) g_loss += v;
}

// ---------------------------------------------------------------------------
__global__ void finish_kernel(float* __restrict__ out)
{
    out[0] = (float)(g_loss / ((double)BN * (double)NPIX));
}

// ---------------------------------------------------------------------------
extern "C" void kernel_launch(void* const* d_in, const int* in_sizes, int n_in,
                              void* d_out, int out_size)
{
    const float* pred   = (const float*)d_in[0];
    const int*   target = (const int*)d_in[1];
    float*       out    = (float*)d_out;

    reset_kernel<<<1, 32>>>();

    // TOTAL/4 float4 elements, 256 threads/block
    bound_kernel<<<(unsigned)(TOTAL / 4 / 256), 256>>>(
        (const float4*)pred, (const int4*)target);

    dim3 grid(HH, BN);
    for (int k = 0; k < 10; ++k) {
        if ((k & 1) == 0) stencil_kernel<0><<<grid, 256>>>();
        else              stencil_kernel<1><<<grid, 256>>>();
        double wgt = (double)((k + 1) * (k + 1));   // (k+1)^alpha, alpha=2
        epilogue_kernel<<<1, 32>>>(wgt);
    }

    finish_kernel<<<1, 1>>>(out);
}

// round 3
// speedup vs baseline: 1.6096x; 1.6096x over previous
#include <cuda_runtime.h>
#include <cuda_fp16.h>

#define BN    32
#define HH    1024
#define WW    1024
#define NPIX  (HH * WW)
#define TOTAL ((size_t)BN * NPIX)
#define ITERS 10

// ---- static scratch (fp16 ping-pong: 64 MB each) ----
__device__ __half g_bufA[TOTAL];
__device__ __half g_bufB[TOTAL];
// per-iteration stats, indexed [k][batch]
__device__ unsigned int g_maxb[ITERS][BN];
__device__ unsigned int g_minb[ITERS][BN];
__device__ double       g_sum [ITERS][BN];

__device__ __forceinline__ float bnd(float p, int t) {
    float v = p - (t == 0 ? 1.0f : 0.0f);
    return v * v;
}

// ---------------------------------------------------------------------------
__global__ void reset_kernel() {
    int i = threadIdx.x;                 // 0 .. ITERS*BN-1
    int k = i / BN, b = i % BN;
    g_maxb[k][b] = 0u;                   // erosion >= 0
    g_minb[k][b] = 0x7f800000u;          // +inf
    g_sum [k][b] = 0.0;
}

// ---------------------------------------------------------------------------
// block-level max/min/sum reduction -> atomics into stats[k][b]
// block = 128 threads (4 warps)
// ---------------------------------------------------------------------------
__device__ __forceinline__ void reduce_stats(float vmax, float vmin, float vsum,
                                             int b, int k)
{
    const int lane = threadIdx.x & 31;
    const int warp = threadIdx.x >> 5;
    #pragma unroll
    for (int d = 16; d > 0; d >>= 1) {
        vmax  = fmaxf(vmax, __shfl_xor_sync(0xffffffffu, vmax, d));
        vmin  = fminf(vmin, __shfl_xor_sync(0xffffffffu, vmin, d));
        vsum +=             __shfl_xor_sync(0xffffffffu, vsum, d);
    }
    __shared__ float smax[4], smin[4], ssum[4];
    if (lane == 0) { smax[warp] = vmax; smin[warp] = vmin; ssum[warp] = vsum; }
    __syncthreads();
    if (warp == 0) {
        vmax = (lane < 4) ? smax[lane] : 0.0f;
        vmin = (lane < 4) ? smin[lane] : __int_as_float(0x7f800000);
        vsum = (lane < 4) ? ssum[lane] : 0.0f;
        #pragma unroll
        for (int d = 2; d > 0; d >>= 1) {
            vmax  = fmaxf(vmax, __shfl_xor_sync(0xffffffffu, vmax, d));
            vmin  = fminf(vmin, __shfl_xor_sync(0xffffffffu, vmin, d));
            vsum +=             __shfl_xor_sync(0xffffffffu, vsum, d);
        }
        if (lane == 0) {
            atomicMax(&g_maxb[k][b], __float_as_uint(vmax));  // vals >= 0
            atomicMin(&g_minb[k][b], __float_as_uint(vmin));
            atomicAdd(&g_sum[k][b], (double)vsum);
        }
    }
}

// ---------------------------------------------------------------------------
// shared stencil core: given c[8] (+l/r halo), u[8], d[8] already affine-
// normalized, compute erosion, store fp16, reduce stats.
// ---------------------------------------------------------------------------
__device__ __forceinline__ void stencil_core(const float c[8], const float u[8],
                                             const float d[8], float l, float r,
                                             __half* outp, int b, int k)
{
    float e[8];
    #pragma unroll
    for (int i = 0; i < 8; ++i) {
        float lf = (i == 0) ? l : c[i - 1];
        float rf = (i == 7) ? r : c[i + 1];
        e[i] = fmaxf(fmaf(0.2f, (c[i] + u[i]) + (d[i] + lf) + rf, -0.5f), 0.0f);
    }
    union { uint4 u4; __half2 h2[4]; } pk;
    #pragma unroll
    for (int j = 0; j < 4; ++j)
        pk.h2[j] = __floats2half2_rn(e[2 * j], e[2 * j + 1]);
    *reinterpret_cast<uint4*>(outp) = pk.u4;

    float vmax = e[0], vmin = e[0], vsum = e[0];
    #pragma unroll
    for (int i = 1; i < 8; ++i) {
        vmax = fmaxf(vmax, e[i]); vmin = fminf(vmin, e[i]); vsum += e[i];
    }
    reduce_stats(vmax, vmin, vsum, b, k);
}

// ---------------------------------------------------------------------------
// Pass 0 (fused): bound = (pred - (tgt==0))^2 computed on the fly for all
// taps; erosion0 -> g_bufA, stats[0].
// grid = (HH, BN), block = 128, 8 px/thread.
// ---------------------------------------------------------------------------
__global__ void __launch_bounds__(128) pass0_kernel(
    const float* __restrict__ pred, const int* __restrict__ tgt)
{
    const int y = blockIdx.x, b = blockIdx.y;
    const int t = threadIdx.x, lane = t & 31;
    const int x0 = t << 3;
    const size_t base = ((size_t)b * HH + y) * WW;
    const float* pr = pred + base;
    const int*   tr = tgt  + base;

    float c[8], u[8], d[8];
    {
        float4 p0 = *(const float4*)(pr + x0);
        float4 p1 = *(const float4*)(pr + x0 + 4);
        int4   q0 = *(const int4*)(tr + x0);
        int4   q1 = *(const int4*)(tr + x0 + 4);
        c[0]=bnd(p0.x,q0.x); c[1]=bnd(p0.y,q0.y); c[2]=bnd(p0.z,q0.z); c[3]=bnd(p0.w,q0.w);
        c[4]=bnd(p1.x,q1.x); c[5]=bnd(p1.y,q1.y); c[6]=bnd(p1.z,q1.z); c[7]=bnd(p1.w,q1.w);
    }
    if (y > 0) {
        float4 p0 = *(const float4*)(pr - WW + x0);
        float4 p1 = *(const float4*)(pr - WW + x0 + 4);
        int4   q0 = *(const int4*)(tr - WW + x0);
        int4   q1 = *(const int4*)(tr - WW + x0 + 4);
        u[0]=bnd(p0.x,q0.x); u[1]=bnd(p0.y,q0.y); u[2]=bnd(p0.z,q0.z); u[3]=bnd(p0.w,q0.w);
        u[4]=bnd(p1.x,q1.x); u[5]=bnd(p1.y,q1.y); u[6]=bnd(p1.z,q1.z); u[7]=bnd(p1.w,q1.w);
    } else {
        #pragma unroll
        for (int i = 0; i < 8; ++i) u[i] = 0.0f;
    }
    if (y < HH - 1) {
        float4 p0 = *(const float4*)(pr + WW + x0);
        float4 p1 = *(const float4*)(pr + WW + x0 + 4);
        int4   q0 = *(const int4*)(tr + WW + x0);
        int4   q1 = *(const int4*)(tr + WW + x0 + 4);
        d[0]=bnd(p0.x,q0.x); d[1]=bnd(p0.y,q0.y); d[2]=bnd(p0.z,q0.z); d[3]=bnd(p0.w,q0.w);
        d[4]=bnd(p1.x,q1.x); d[5]=bnd(p1.y,q1.y); d[6]=bnd(p1.z,q1.z); d[7]=bnd(p1.w,q1.w);
    } else {
        #pragma unroll
        for (int i = 0; i < 8; ++i) d[i] = 0.0f;
    }

    float l = __shfl_up_sync(0xffffffffu, c[7], 1);
    if (lane == 0)  l = (x0 > 0)       ? bnd(pr[x0 - 1], tr[x0 - 1]) : 0.0f;
    float r = __shfl_down_sync(0xffffffffu, c[0], 1);
    if (lane == 31) r = (x0 + 8 < WW)  ? bnd(pr[x0 + 8], tr[x0 + 8]) : 0.0f;

    stencil_core(c, u, d, l, r, g_bufA + base + x0, b, 0);
}

// ---------------------------------------------------------------------------
// Passes 1..9: read fp16 buffer, affine-normalize with stats[k-1], stencil,
// write other fp16 buffer, accumulate stats[k].
// DIR==0: A->B, DIR==1: B->A. grid = (HH, BN), block = 128, 8 px/thread.
// ---------------------------------------------------------------------------
template <int DIR>
__global__ void __launch_bounds__(128) stencil_kernel(int k)
{
    const __half* __restrict__ in  = DIR ? g_bufB : g_bufA;
    __half*       __restrict__ out = DIR ? g_bufA : g_bufB;

    const int y = blockIdx.x, b = blockIdx.y;
    const int t = threadIdx.x, lane = t & 31;
    const int x0 = t << 3;
    const size_t base = ((size_t)b * HH + y) * WW;

    const float emax = __uint_as_float(g_maxb[k - 1][b]);
    const float emin = __uint_as_float(g_minb[k - 1][b]);
    const float den  = emax - emin;
    const float s = (den != 0.0f) ? 1.0f / den   : 1.0f;
    const float o = (den != 0.0f) ? -emin / den  : 0.0f;

    const __half* rowc = in + base;

    float c[8], u[8], d[8];
    {
        union { uint4 u4; __half2 h2[4]; } lc;
        lc.u4 = *(const uint4*)(rowc + x0);
        #pragma unroll
        for (int j = 0; j < 4; ++j) {
            float2 f = __half22float2(lc.h2[j]);
            c[2*j]   = fmaf(f.x, s, o);
            c[2*j+1] = fmaf(f.y, s, o);
        }
    }
    if (y > 0) {
        union { uint4 u4; __half2 h2[4]; } lc;
        lc.u4 = *(const uint4*)(rowc - WW + x0);
        #pragma unroll
        for (int j = 0; j < 4; ++j) {
            float2 f = __half22float2(lc.h2[j]);
            u[2*j]   = fmaf(f.x, s, o);
            u[2*j+1] = fmaf(f.y, s, o);
        }
    } else {
        #pragma unroll
        for (int i = 0; i < 8; ++i) u[i] = 0.0f;
    }
    if (y < HH - 1) {
        union { uint4 u4; __half2 h2[4]; } lc;
        lc.u4 = *(const uint4*)(rowc + WW + x0);
        #pragma unroll
        for (int j = 0; j < 4; ++j) {
            float2 f = __half22float2(lc.h2[j]);
            d[2*j]   = fmaf(f.x, s, o);
            d[2*j+1] = fmaf(f.y, s, o);
        }
    } else {
        #pragma unroll
        for (int i = 0; i < 8; ++i) d[i] = 0.0f;
    }

    float l = __shfl_up_sync(0xffffffffu, c[7], 1);
    if (lane == 0)  l = (x0 > 0)      ? fmaf(__half2float(rowc[x0 - 1]), s, o) : 0.0f;
    float r = __shfl_down_sync(0xffffffffu, c[0], 1);
    if (lane == 31) r = (x0 + 8 < WW) ? fmaf(__half2float(rowc[x0 + 8]), s, o) : 0.0f;

    stencil_core(c, u, d, l, r, out + base + x0, b, k);
}

// ---------------------------------------------------------------------------
// Final: analytic loss from the 10 stat triples.
//   sum(normalized_k) = (S_k - N*min_k)/denom_k   (or S_k if denom==0)
//   loss = sum_k contrib_k * (k+1)^2 / (BN*NPIX)
// ---------------------------------------------------------------------------
__global__ void finish_kernel(float* __restrict__ out)
{
    const int b = threadIdx.x;    // 0..31
    double loss = 0.0;
    #pragma unroll
    for (int k = 0; k < ITERS; ++k) {
        float emax = __uint_as_float(g_maxb[k][b]);
        float emin = __uint_as_float(g_minb[k][b]);
        double S   = g_sum[k][b];
        float den  = emax - emin;
        double contrib = (den != 0.0f)
            ? (S - (double)NPIX * (double)emin) / (double)den
            : S;
        loss += contrib * (double)((k + 1) * (k + 1));
    }
    #pragma unroll
    for (int d = 16; d > 0; d >>= 1)
        loss += __shfl_xor_sync(0xffffffffu, loss, d);
    if (b == 0)
        out[0] = (float)(loss / ((double)BN * (double)NPIX));
}

// ---------------------------------------------------------------------------
extern "C" void kernel_launch(void* const* d_in, const int* in_sizes, int n_in,
                              void* d_out, int out_size)
{
    const float* pred   = (const float*)d_in[0];
    const int*   target = (const int*)d_in[1];
    float*       out    = (float*)d_out;

    reset_kernel<<<1, ITERS * BN>>>();

    dim3 grid(HH, BN);
    pass0_kernel<<<grid, 128>>>(pred, target);

    for (int k = 1; k < ITERS; ++k) {
        if (k & 1) stencil_kernel<0><<<grid, 128>>>(k);   // A -> B
        else       stencil_kernel<1><<<grid, 128>>>(k);   // B -> A
    }

    finish_kernel<<<1, 32>>>(out);
}

// round 4
// speedup vs baseline: 1.9476x; 1.2100x over previous
#include <cuda_runtime.h>
#include <cuda_fp16.h>

#define BN    32
#define HH    1024
#define WW    1024
#define NPIX  (HH * WW)
#define TOTAL ((size_t)BN * NPIX)
#define ITERS 10
#define RY    8

// ---- static scratch (fp16 ping-pong: 64 MB each) ----
__device__ __half g_bufA[TOTAL];
__device__ __half g_bufB[TOTAL];
// per-iteration stats, indexed [k][batch]
__device__ unsigned int g_maxb[ITERS][BN];
__device__ unsigned int g_minb[ITERS][BN];
__device__ double       g_sum [ITERS][BN];

__device__ __forceinline__ float bnd(float p, int t) {
    float v = p - (t == 0 ? 1.0f : 0.0f);
    return v * v;
}

// ---------------------------------------------------------------------------
__global__ void reset_kernel() {
    int i = threadIdx.x;                 // 0 .. ITERS*BN-1
    int k = i / BN, b = i % BN;
    g_maxb[k][b] = 0u;                   // erosion >= 0
    g_minb[k][b] = 0x7f800000u;          // +inf
    g_sum [k][b] = 0.0;
}

// ---------------------------------------------------------------------------
// block reduction (128 threads) -> atomics into stats[k][b]
// ---------------------------------------------------------------------------
__device__ __forceinline__ void reduce_stats(float vmax, float vmin, float vsum,
                                             int b, int k)
{
    const int lane = threadIdx.x & 31;
    const int warp = threadIdx.x >> 5;
    #pragma unroll
    for (int d = 16; d > 0; d >>= 1) {
        vmax  = fmaxf(vmax, __shfl_xor_sync(0xffffffffu, vmax, d));
        vmin  = fminf(vmin, __shfl_xor_sync(0xffffffffu, vmin, d));
        vsum +=             __shfl_xor_sync(0xffffffffu, vsum, d);
    }
    __shared__ float smax[4], smin[4], ssum[4];
    if (lane == 0) { smax[warp] = vmax; smin[warp] = vmin; ssum[warp] = vsum; }
    __syncthreads();
    if (warp == 0) {
        vmax = (lane < 4) ? smax[lane] : 0.0f;
        vmin = (lane < 4) ? smin[lane] : __int_as_float(0x7f800000);
        vsum = (lane < 4) ? ssum[lane] : 0.0f;
        #pragma unroll
        for (int d = 2; d > 0; d >>= 1) {
            vmax  = fmaxf(vmax, __shfl_xor_sync(0xffffffffu, vmax, d));
            vmin  = fminf(vmin, __shfl_xor_sync(0xffffffffu, vmin, d));
            vsum +=             __shfl_xor_sync(0xffffffffu, vsum, d);
        }
        if (lane == 0) {
            atomicMax(&g_maxb[k][b], __float_as_uint(vmax));  // vals >= 0
            atomicMin(&g_minb[k][b], __float_as_uint(vmin));
            atomicAdd(&g_sum[k][b], (double)vsum);
        }
    }
}

// ---------------------------------------------------------------------------
// Stencil passes 1..9 with vertical register rolling over an RY-row strip.
// DIR==0: A->B, DIR==1: B->A. grid = (HH/RY, BN), block = 128, 8 px/thread.
// ---------------------------------------------------------------------------
template <int DIR>
__global__ void __launch_bounds__(128) stencil_kernel(int k)
{
    const __half* __restrict__ in  = DIR ? g_bufB : g_bufA;
    __half*       __restrict__ out = DIR ? g_bufA : g_bufB;

    const int b    = blockIdx.y;
    const int y0   = blockIdx.x * RY;
    const int t    = threadIdx.x;
    const int lane = t & 31;
    const int x0   = t << 3;
    const size_t bb = (size_t)b * NPIX;

    const float emax = __uint_as_float(g_maxb[k - 1][b]);
    const float emin = __uint_as_float(g_minb[k - 1][b]);
    const float den  = emax - emin;
    const float s = (den != 0.0f) ? 1.0f / den  : 1.0f;
    const float o = (den != 0.0f) ? -emin / den : 0.0f;

    float rv[3][8];          // normalized rolling rows
    float rhl[3], rhr[3];    // per-row halos

    auto loadrow = [&](int slot, int y) {
        if ((unsigned)y < (unsigned)HH) {   // uniform branch per block
            const __half* rp = in + bb + (size_t)y * WW;
            uint4 raw = *reinterpret_cast<const uint4*>(rp + x0);
            const __half2* h = reinterpret_cast<const __half2*>(&raw);
            #pragma unroll
            for (int j = 0; j < 4; ++j) {
                float2 f = __half22float2(h[j]);
                rv[slot][2 * j]     = fmaf(f.x, s, o);
                rv[slot][2 * j + 1] = fmaf(f.y, s, o);
            }
            float l = __shfl_up_sync(0xffffffffu, rv[slot][7], 1);
            if (lane == 0)  l = (x0 > 0)      ? fmaf(__half2float(rp[x0 - 1]), s, o) : 0.0f;
            float r = __shfl_down_sync(0xffffffffu, rv[slot][0], 1);
            if (lane == 31) r = (x0 + 8 < WW) ? fmaf(__half2float(rp[x0 + 8]), s, o) : 0.0f;
            rhl[slot] = l; rhr[slot] = r;
        } else {
            #pragma unroll
            for (int j = 0; j < 8; ++j) rv[slot][j] = 0.0f;
            rhl[slot] = rhr[slot] = 0.0f;
        }
    };

    loadrow(0, y0 - 1);
    loadrow(1, y0);

    float vsum = 0.0f;
    __half2 hmax2 = __float2half2_rn(0.0f);
    __half2 hmin2 = __float2half2_rn(65504.0f);

    #pragma unroll
    for (int i = 0; i < RY; ++i) {
        const int y = y0 + i;
        const int pslot = i % 3, cslot = (i + 1) % 3, nslot = (i + 2) % 3;
        loadrow(nslot, y + 1);

        const float* P  = rv[pslot];
        const float* C  = rv[cslot];
        const float* Nr = rv[nslot];

        float e[8];
        #pragma unroll
        for (int j = 0; j < 8; ++j) {
            float lf = (j == 0) ? rhl[cslot] : C[j - 1];
            float rf = (j == 7) ? rhr[cslot] : C[j + 1];
            e[j] = fmaxf(fmaf(0.2f, (C[j] + P[j]) + (Nr[j] + lf) + rf, -0.5f), 0.0f);
        }

        union { uint4 u4; __half2 h2[4]; } pk;
        #pragma unroll
        for (int j = 0; j < 4; ++j)
            pk.h2[j] = __floats2half2_rn(e[2 * j], e[2 * j + 1]);
        *reinterpret_cast<uint4*>(out + bb + (size_t)y * WW + x0) = pk.u4;

        #pragma unroll
        for (int j = 0; j < 4; ++j) {
            hmax2 = __hmax2(hmax2, pk.h2[j]);
            hmin2 = __hmin2(hmin2, pk.h2[j]);
        }
        vsum += ((e[0] + e[1]) + (e[2] + e[3])) + ((e[4] + e[5]) + (e[6] + e[7]));
    }

    float vmax = fmaxf(__low2float(hmax2), __high2float(hmax2));
    float vmin = fminf(__low2float(hmin2), __high2float(hmin2));
    reduce_stats(vmax, vmin, vsum, b, k);
}

// ---------------------------------------------------------------------------
// Pass 0 (fused bound + erosion0) with the same rolling-strip structure.
// ---------------------------------------------------------------------------
__global__ void __launch_bounds__(128) pass0_kernel(
    const float* __restrict__ pred, const int* __restrict__ tgt)
{
    const int b    = blockIdx.y;
    const int y0   = blockIdx.x * RY;
    const int t    = threadIdx.x;
    const int lane = t & 31;
    const int x0   = t << 3;
    const size_t bb = (size_t)b * NPIX;

    float rv[3][8];
    float rhl[3], rhr[3];

    auto loadrow = [&](int slot, int y) {
        if ((unsigned)y < (unsigned)HH) {
            const float* pr  = pred + bb + (size_t)y * WW;
            const int*   trw = tgt  + bb + (size_t)y * WW;
            float4 p0 = *(const float4*)(pr + x0);
            float4 p1 = *(const float4*)(pr + x0 + 4);
            int4   q0 = *(const int4*)(trw + x0);
            int4   q1 = *(const int4*)(trw + x0 + 4);
            rv[slot][0] = bnd(p0.x, q0.x); rv[slot][1] = bnd(p0.y, q0.y);
            rv[slot][2] = bnd(p0.z, q0.z); rv[slot][3] = bnd(p0.w, q0.w);
            rv[slot][4] = bnd(p1.x, q1.x); rv[slot][5] = bnd(p1.y, q1.y);
            rv[slot][6] = bnd(p1.z, q1.z); rv[slot][7] = bnd(p1.w, q1.w);
            float l = __shfl_up_sync(0xffffffffu, rv[slot][7], 1);
            if (lane == 0)  l = (x0 > 0)      ? bnd(pr[x0 - 1], trw[x0 - 1]) : 0.0f;
            float r = __shfl_down_sync(0xffffffffu, rv[slot][0], 1);
            if (lane == 31) r = (x0 + 8 < WW) ? bnd(pr[x0 + 8], trw[x0 + 8]) : 0.0f;
            rhl[slot] = l; rhr[slot] = r;
        } else {
            #pragma unroll
            for (int j = 0; j < 8; ++j) rv[slot][j] = 0.0f;
            rhl[slot] = rhr[slot] = 0.0f;
        }
    };

    loadrow(0, y0 - 1);
    loadrow(1, y0);

    float vsum = 0.0f;
    __half2 hmax2 = __float2half2_rn(0.0f);
    __half2 hmin2 = __float2half2_rn(65504.0f);

    #pragma unroll
    for (int i = 0; i < RY; ++i) {
        const int y = y0 + i;
        const int pslot = i % 3, cslot = (i + 1) % 3, nslot = (i + 2) % 3;
        loadrow(nslot, y + 1);

        const float* P  = rv[pslot];
        const float* C  = rv[cslot];
        const float* Nr = rv[nslot];

        float e[8];
        #pragma unroll
        for (int j = 0; j < 8; ++j) {
            float lf = (j == 0) ? rhl[cslot] : C[j - 1];
            float rf = (j == 7) ? rhr[cslot] : C[j + 1];
            e[j] = fmaxf(fmaf(0.2f, (C[j] + P[j]) + (Nr[j] + lf) + rf, -0.5f), 0.0f);
        }

        union { uint4 u4; __half2 h2[4]; } pk;
        #pragma unroll
        for (int j = 0; j < 4; ++j)
            pk.h2[j] = __floats2half2_rn(e[2 * j], e[2 * j + 1]);
        *reinterpret_cast<uint4*>(g_bufA + bb + (size_t)y * WW + x0) = pk.u4;

        #pragma unroll
        for (int j = 0; j < 4; ++j) {
            hmax2 = __hmax2(hmax2, pk.h2[j]);
            hmin2 = __hmin2(hmin2, pk.h2[j]);
        }
        vsum += ((e[0] + e[1]) + (e[2] + e[3])) + ((e[4] + e[5]) + (e[6] + e[7]));
    }

    float vmax = fmaxf(__low2float(hmax2), __high2float(hmax2));
    float vmin = fminf(__low2float(hmin2), __high2float(hmin2));
    reduce_stats(vmax, vmin, vsum, b, 0);
}

// ---------------------------------------------------------------------------
// Final: analytic loss from the 10 stat triples.
// ---------------------------------------------------------------------------
__global__ void finish_kernel(float* __restrict__ out)
{
    const int b = threadIdx.x;    // 0..31
    double loss = 0.0;
    #pragma unroll
    for (int k = 0; k < ITERS; ++k) {
        float emax = __uint_as_float(g_maxb[k][b]);
        float emin = __uint_as_float(g_minb[k][b]);
        double S   = g_sum[k][b];
        float den  = emax - emin;
        double contrib = (den != 0.0f)
            ? (S - (double)NPIX * (double)emin) / (double)den
            : S;
        loss += contrib * (double)((k + 1) * (k + 1));
    }
    #pragma unroll
    for (int d = 16; d > 0; d >>= 1)
        loss += __shfl_xor_sync(0xffffffffu, loss, d);
    if (b == 0)
        out[0] = (float)(loss / ((double)BN * (double)NPIX));
}

// ---------------------------------------------------------------------------
extern "C" void kernel_launch(void* const* d_in, const int* in_sizes, int n_in,
                              void* d_out, int out_size)
{
    const float* pred   = (const float*)d_in[0];
    const int*   target = (const int*)d_in[1];
    float*       out    = (float*)d_out;

    reset_kernel<<<1, ITERS * BN>>>();

    dim3 grid(HH / RY, BN);
    pass0_kernel<<<grid, 128>>>(pred, target);

    for (int k = 1; k < ITERS; ++k) {
        if (k & 1) stencil_kernel<0><<<grid, 128>>>(k);   // A -> B
        else       stencil_kernel<1><<<grid, 128>>>(k);   // B -> A
    }

    finish_kernel<<<1, 32>>>(out);
}

// round 5
// speedup vs baseline: 2.7986x; 1.4370x over previous
#include <cuda_runtime.h>
#include <cuda_fp16.h>

#define BN    32
#define HH    1024
#define WW    1024
#define NPIX  (HH * WW)
#define TOTAL ((size_t)BN * NPIX)
#define ITERS 10
#define RY    8

// ---- static scratch (fp16 ping-pong: 64 MB each) ----
__device__ __half g_bufA[TOTAL];
__device__ __half g_bufB[TOTAL];
// per-iteration stats, indexed [k][batch]
__device__ unsigned int g_maxb[ITERS][BN];
__device__ unsigned int g_minb[ITERS][BN];
__device__ double       g_sum [ITERS][BN];

__device__ __forceinline__ float bnd(float p, int t) {
    float v = p - (t == 0 ? 1.0f : 0.0f);
    return v * v;
}
__device__ __forceinline__ __half2 U2H(unsigned u) {
    return *reinterpret_cast<__half2*>(&u);
}
__device__ __forceinline__ unsigned H2U(__half2 h) {
    return *reinterpret_cast<unsigned*>(&h);
}

// ---------------------------------------------------------------------------
__global__ void reset_kernel() {
    int i = threadIdx.x;                 // 0 .. ITERS*BN-1
    int k = i / BN, b = i % BN;
    g_maxb[k][b] = 0u;                   // erosion >= 0
    g_minb[k][b] = 0x7f800000u;          // +inf
    g_sum [k][b] = 0.0;
}

// ---------------------------------------------------------------------------
// block reduction (128 threads) -> atomics into stats[k][b]
// ---------------------------------------------------------------------------
__device__ __forceinline__ void reduce_stats(float vmax, float vmin, float vsum,
                                             int b, int k)
{
    const int lane = threadIdx.x & 31;
    const int warp = threadIdx.x >> 5;
    #pragma unroll
    for (int d = 16; d > 0; d >>= 1) {
        vmax  = fmaxf(vmax, __shfl_xor_sync(0xffffffffu, vmax, d));
        vmin  = fminf(vmin, __shfl_xor_sync(0xffffffffu, vmin, d));
        vsum +=             __shfl_xor_sync(0xffffffffu, vsum, d);
    }
    __shared__ float smax[4], smin[4], ssum[4];
    if (lane == 0) { smax[warp] = vmax; smin[warp] = vmin; ssum[warp] = vsum; }
    __syncthreads();
    if (warp == 0) {
        vmax = (lane < 4) ? smax[lane] : 0.0f;
        vmin = (lane < 4) ? smin[lane] : __int_as_float(0x7f800000);
        vsum = (lane < 4) ? ssum[lane] : 0.0f;
        #pragma unroll
        for (int d = 2; d > 0; d >>= 1) {
            vmax  = fmaxf(vmax, __shfl_xor_sync(0xffffffffu, vmax, d));
            vmin  = fminf(vmin, __shfl_xor_sync(0xffffffffu, vmin, d));
            vsum +=             __shfl_xor_sync(0xffffffffu, vsum, d);
        }
        if (lane == 0) {
            atomicMax(&g_maxb[k][b], __float_as_uint(vmax));  // vals >= 0
            atomicMin(&g_minb[k][b], __float_as_uint(vmin));
            atomicAdd(&g_sum[k][b], (double)vsum);
        }
    }
}

// ---------------------------------------------------------------------------
// Stencil passes 1..9 in packed half2 arithmetic with vertical register
// rolling over an RY-row strip.  DIR==0: A->B, DIR==1: B->A.
// grid = (HH/RY, BN), block = 128, 8 px/thread (4 half2 regs/row).
// ---------------------------------------------------------------------------
template <int DIR>
__global__ void __launch_bounds__(128) stencil_kernel(int k)
{
    const __half* __restrict__ in  = DIR ? g_bufB : g_bufA;
    __half*       __restrict__ out = DIR ? g_bufA : g_bufB;

    const int b    = blockIdx.y;
    const int y0   = blockIdx.x * RY;
    const int t    = threadIdx.x;
    const int lane = t & 31;
    const int x0   = t << 3;
    const size_t bb = (size_t)b * NPIX;

    const float emax = __uint_as_float(g_maxb[k - 1][b]);
    const float emin = __uint_as_float(g_minb[k - 1][b]);
    const float den  = emax - emin;
    const float sf = (den != 0.0f) ? 1.0f / den  : 1.0f;
    const float of = (den != 0.0f) ? -emin / den : 0.0f;
    const __half2 s2 = __float2half2_rn(sf);
    const __half2 o2 = __float2half2_rn(of);
    const __half  sh = __low2half(s2);
    const __half  oh = __low2half(o2);
    const __half2 c02  = __float2half2_rn(0.2f);
    const __half2 cm05 = __float2half2_rn(-0.5f);
    const __half2 zero2 = __float2half2_rn(0.0f);

    unsigned rw[3][4];            // normalized rows (half2 as uint)
    unsigned eL[3], eR[3];        // halo regs: use .hi of eL, .lo of eR

    auto loadrow = [&](int slot, int y) {
        if ((unsigned)y < (unsigned)HH) {   // uniform per block
            const __half* rp = in + bb + (size_t)y * WW;
            uint4 raw = *reinterpret_cast<const uint4*>(rp + x0);
            rw[slot][0] = H2U(__hfma2(U2H(raw.x), s2, o2));
            rw[slot][1] = H2U(__hfma2(U2H(raw.y), s2, o2));
            rw[slot][2] = H2U(__hfma2(U2H(raw.z), s2, o2));
            rw[slot][3] = H2U(__hfma2(U2H(raw.w), s2, o2));
            unsigned L = __shfl_up_sync(0xffffffffu, rw[slot][3], 1);
            unsigned R = __shfl_down_sync(0xffffffffu, rw[slot][0], 1);
            if (lane == 0)
                L = (x0 > 0)
                  ? ((unsigned)__half_as_ushort(__hfma(rp[x0 - 1], sh, oh)) << 16)
                  : 0u;
            if (lane == 31)
                R = (x0 + 8 < WW)
                  ? (unsigned)__half_as_ushort(__hfma(rp[x0 + 8], sh, oh))
                  : 0u;
            eL[slot] = L; eR[slot] = R;
        } else {
            rw[slot][0] = rw[slot][1] = rw[slot][2] = rw[slot][3] = 0u;
            eL[slot] = eR[slot] = 0u;
        }
    };

    loadrow(0, y0 - 1);
    loadrow(1, y0);

    float vsum = 0.0f;
    __half2 hmax2 = zero2;
    __half2 hmin2 = __float2half2_rn(65504.0f);

    #pragma unroll
    for (int i = 0; i < RY; ++i) {
        const int y = y0 + i;
        const int pslot = i % 3, cslot = (i + 1) % 3, nslot = (i + 2) % 3;
        loadrow(nslot, y + 1);

        const unsigned* C  = rw[cslot];
        const unsigned* P  = rw[pslot];
        const unsigned* Nx = rw[nslot];

        // extended row: E[0]=left halo (.hi valid), E[1..4]=C, E[5]=right halo (.lo valid)
        unsigned E0 = eL[cslot], E5 = eR[cslot];
        unsigned tt[5];
        tt[0] = __byte_perm(E0,   C[0], 0x5432);
        tt[1] = __byte_perm(C[0], C[1], 0x5432);
        tt[2] = __byte_perm(C[1], C[2], 0x5432);
        tt[3] = __byte_perm(C[2], C[3], 0x5432);
        tt[4] = __byte_perm(C[3], E5,   0x5432);

        __half2 e[4];
        #pragma unroll
        for (int j = 0; j < 4; ++j) {
            __half2 vert  = __hadd2(__hadd2(U2H(C[j]), U2H(P[j])), U2H(Nx[j]));
            __half2 horiz = __hadd2(U2H(tt[j]), U2H(tt[j + 1]));
            __half2 sm    = __hadd2(vert, horiz);
            e[j] = __hmax2(__hfma2(sm, c02, cm05), zero2);
        }

        uint4 pk;
        pk.x = H2U(e[0]); pk.y = H2U(e[1]); pk.z = H2U(e[2]); pk.w = H2U(e[3]);
        *reinterpret_cast<uint4*>(out + bb + (size_t)y * WW + x0) = pk;

        hmax2 = __hmax2(hmax2, __hmax2(__hmax2(e[0], e[1]), __hmax2(e[2], e[3])));
        hmin2 = __hmin2(hmin2, __hmin2(__hmin2(e[0], e[1]), __hmin2(e[2], e[3])));
        __half2 sr = __hadd2(__hadd2(e[0], e[1]), __hadd2(e[2], e[3]));
        float2 f = __half22float2(sr);
        vsum += f.x + f.y;
    }

    float vmax = fmaxf(__low2float(hmax2), __high2float(hmax2));
    float vmin = fminf(__low2float(hmin2), __high2float(hmin2));
    reduce_stats(vmax, vmin, vsum, b, k);
}

// ---------------------------------------------------------------------------
// Pass 0 (fused bound + erosion0), fp32 compute (input-bandwidth-bound).
// ---------------------------------------------------------------------------
__global__ void __launch_bounds__(128) pass0_kernel(
    const float* __restrict__ pred, const int* __restrict__ tgt)
{
    const int b    = blockIdx.y;
    const int y0   = blockIdx.x * RY;
    const int t    = threadIdx.x;
    const int lane = t & 31;
    const int x0   = t << 3;
    const size_t bb = (size_t)b * NPIX;

    float rv[3][8];
    float rhl[3], rhr[3];

    auto loadrow = [&](int slot, int y) {
        if ((unsigned)y < (unsigned)HH) {
            const float* pr  = pred + bb + (size_t)y * WW;
            const int*   trw = tgt  + bb + (size_t)y * WW;
            float4 p0 = *(const float4*)(pr + x0);
            float4 p1 = *(const float4*)(pr + x0 + 4);
            int4   q0 = *(const int4*)(trw + x0);
            int4   q1 = *(const int4*)(trw + x0 + 4);
            rv[slot][0] = bnd(p0.x, q0.x); rv[slot][1] = bnd(p0.y, q0.y);
            rv[slot][2] = bnd(p0.z, q0.z); rv[slot][3] = bnd(p0.w, q0.w);
            rv[slot][4] = bnd(p1.x, q1.x); rv[slot][5] = bnd(p1.y, q1.y);
            rv[slot][6] = bnd(p1.z, q1.z); rv[slot][7] = bnd(p1.w, q1.w);
            float l = __shfl_up_sync(0xffffffffu, rv[slot][7], 1);
            if (lane == 0)  l = (x0 > 0)      ? bnd(pr[x0 - 1], trw[x0 - 1]) : 0.0f;
            float r = __shfl_down_sync(0xffffffffu, rv[slot][0], 1);
            if (lane == 31) r = (x0 + 8 < WW) ? bnd(pr[x0 + 8], trw[x0 + 8]) : 0.0f;
            rhl[slot] = l; rhr[slot] = r;
        } else {
            #pragma unroll
            for (int j = 0; j < 8; ++j) rv[slot][j] = 0.0f;
            rhl[slot] = rhr[slot] = 0.0f;
        }
    };

    loadrow(0, y0 - 1);
    loadrow(1, y0);

    float vsum = 0.0f;
    __half2 hmax2 = __float2half2_rn(0.0f);
    __half2 hmin2 = __float2half2_rn(65504.0f);

    #pragma unroll
    for (int i = 0; i < RY; ++i) {
        const int y = y0 + i;
        const int pslot = i % 3, cslot = (i + 1) % 3, nslot = (i + 2) % 3;
        loadrow(nslot, y + 1);

        const float* P  = rv[pslot];
        const float* C  = rv[cslot];
        const float* Nr = rv[nslot];

        float e[8];
        #pragma unroll
        for (int j = 0; j < 8; ++j) {
            float lf = (j == 0) ? rhl[cslot] : C[j - 1];
            float rf = (j == 7) ? rhr[cslot] : C[j + 1];
            e[j] = fmaxf(fmaf(0.2f, (C[j] + P[j]) + (Nr[j] + lf) + rf, -0.5f), 0.0f);
        }

        union { uint4 u4; __half2 h2[4]; } pk;
        #pragma unroll
        for (int j = 0; j < 4; ++j)
            pk.h2[j] = __floats2half2_rn(e[2 * j], e[2 * j + 1]);
        *reinterpret_cast<uint4*>(g_bufA + bb + (size_t)y * WW + x0) = pk.u4;

        #pragma unroll
        for (int j = 0; j < 4; ++j) {
            hmax2 = __hmax2(hmax2, pk.h2[j]);
            hmin2 = __hmin2(hmin2, pk.h2[j]);
        }
        vsum += ((e[0] + e[1]) + (e[2] + e[3])) + ((e[4] + e[5]) + (e[6] + e[7]));
    }

    float vmax = fmaxf(__low2float(hmax2), __high2float(hmax2));
    float vmin = fminf(__low2float(hmin2), __high2float(hmin2));
    reduce_stats(vmax, vmin, vsum, b, 0);
}

// ---------------------------------------------------------------------------
// Final: analytic loss from the 10 stat triples.
// ---------------------------------------------------------------------------
__global__ void finish_kernel(float* __restrict__ out)
{
    const int b = threadIdx.x;    // 0..31
    double loss = 0.0;
    #pragma unroll
    for (int k = 0; k < ITERS; ++k) {
        float emax = __uint_as_float(g_maxb[k][b]);
        float emin = __uint_as_float(g_minb[k][b]);
        double S   = g_sum[k][b];
        float den  = emax - emin;
        double contrib = (den != 0.0f)
            ? (S - (double)NPIX * (double)emin) / (double)den
            : S;
        loss += contrib * (double)((k + 1) * (k + 1));
    }
    #pragma unroll
    for (int d = 16; d > 0; d >>= 1)
        loss += __shfl_xor_sync(0xffffffffu, loss, d);
    if (b == 0)
        out[0] = (float)(loss / ((double)BN * (double)NPIX));
}

// ---------------------------------------------------------------------------
extern "C" void kernel_launch(void* const* d_in, const int* in_sizes, int n_in,
                              void* d_out, int out_size)
{
    const float* pred   = (const float*)d_in[0];
    const int*   target = (const int*)d_in[1];
    float*       out    = (float*)d_out;

    reset_kernel<<<1, ITERS * BN>>>();

    dim3 grid(HH / RY, BN);
    pass0_kernel<<<grid, 128>>>(pred, target);

    for (int k = 1; k < ITERS; ++k) {
        if (k & 1) stencil_kernel<0><<<grid, 128>>>(k);   // A -> B
        else       stencil_kernel<1><<<grid, 128>>>(k);   // B -> A
    }

    finish_kernel<<<1, 32>>>(out);
}